// round 1
// baseline (speedup 1.0000x reference)
#include <cuda_runtime.h>
#include <math.h>

#define B_   512
#define L_   512
#define E_   100
#define F_   100
#define H_   100
#define KK_  10
#define LT_  128

// ---------------- scratch (device globals; no allocations) ----------------
__device__ float g_h[B_ * F_ * L_];          // 104.8 MB  h = relu(conv1)
__device__ float g_logits[B_ * L_];          // 1 MB
__device__ float g_gz[B_ * F_];              // per-batch global half of conv3 (+bias)
__device__ float g_W1t[3 * 100 * 128];       // transposed/padded conv weights [dx][e][f]
__device__ float g_W2t[3 * 100 * 128];
__device__ float g_WLt[3 * 100 * 128];

// ---------------- K0: weight transpose [F][E][3] -> [3][E][128(F pad)] ----
__global__ void k0_prep(const float* __restrict__ w1, const float* __restrict__ w2,
                        const float* __restrict__ wl) {
    int idx = blockIdx.x * 256 + threadIdx.x;
    if (idx >= 3 * 100 * 128) return;
    int dx = idx / (100 * 128);
    int rem = idx - dx * (100 * 128);
    int e = rem >> 7;
    int f = rem & 127;
    float v1 = 0.f, v2 = 0.f, v3 = 0.f;
    if (f < 100) {
        int src = f * 300 + e * 3 + dx;
        v1 = w1[src]; v2 = w2[src]; v3 = wl[src];
    }
    g_W1t[idx] = v1; g_W2t[idx] = v2; g_WLt[idx] = v3;
}

// ---------------- shared conv GEMM core -----------------------------------
// Block of 256 threads computes out[f][n] = sum_{e<100,dx<3} W[dx][e][f] * sIn[e][n+dx]
// for f in [0,128) (rows >=100 are zero-padded weights), n = tx + j*16, j<TN.
// acc persists across the 3 dx chunks. Weight chunk staged in sW [100][128].
template <int TN>
__device__ __forceinline__ void conv_core(const float* __restrict__ Wt,
                                          const float* sIn, int inStride,
                                          float* sW, float acc[8][TN]) {
    const int tid = threadIdx.x;
    const int tx = tid & 15;
    const int ty = tid >> 4;
#pragma unroll
    for (int i = 0; i < 8; i++)
#pragma unroll
        for (int j = 0; j < TN; j++) acc[i][j] = 0.f;

    for (int dx = 0; dx < 3; dx++) {
        for (int idx = tid; idx < 100 * 128; idx += 256)
            sW[idx] = Wt[dx * 100 * 128 + idx];
        __syncthreads();
#pragma unroll 2
        for (int e = 0; e < 100; e++) {
            const float4* w4 = reinterpret_cast<const float4*>(&sW[e * 128 + ty * 8]);
            float4 a0 = w4[0], a1 = w4[1];
            float a[8] = {a0.x, a0.y, a0.z, a0.w, a1.x, a1.y, a1.z, a1.w};
            const float* xrow = &sIn[e * inStride + tx + dx];
            float bfr[TN];
#pragma unroll
            for (int j = 0; j < TN; j++) bfr[j] = xrow[j * 16];
#pragma unroll
            for (int i = 0; i < 8; i++)
#pragma unroll
                for (int j = 0; j < TN; j++)
                    acc[i][j] = fmaf(a[i], bfr[j], acc[i][j]);
        }
        __syncthreads();
    }
}

// ---------------- K1: embedding gather + conv1 -> g_h ---------------------
__global__ __launch_bounds__(256) void k1_conv1(const int* __restrict__ x,
                                                const float* __restrict__ emb,
                                                const float* __restrict__ b1) {
    extern __shared__ float smem[];
    float* sE = smem;                 // [100][132]
    float* sW = smem + 100 * 132;     // [100*128]
    const int b = blockIdx.y;
    const int l0 = blockIdx.x * LT_;
    const int tid = threadIdx.x;

    // load e^T tile with halo 1: sE[e][c] = emb[x[b][l0-1+c]][e], c in [0,130)
    for (int idx = tid; idx < 130 * 100; idx += 256) {
        int c = idx / 100;
        int e = idx - c * 100;
        int l = l0 - 1 + c;
        float v = 0.f;
        if ((unsigned)l < (unsigned)L_) {
            int row = x[b * L_ + l];
            v = emb[row * E_ + e];
        }
        sE[e * 132 + c] = v;
    }
    for (int e = tid; e < 100; e += 256) { sE[e * 132 + 130] = 0.f; sE[e * 132 + 131] = 0.f; }
    __syncthreads();

    float acc[8][8];
    conv_core<8>(g_W1t, sE, 132, sW, acc);

    const int tx = tid & 15, ty = tid >> 4;
#pragma unroll
    for (int i = 0; i < 8; i++) {
        int f = ty * 8 + i;
        if (f < 100) {
            float bb = b1[f];
            float* dst = &g_h[(b * F_ + f) * L_ + l0];
#pragma unroll
            for (int j = 0; j < 8; j++) {
                int n = tx + j * 16;
                dst[n] = fmaxf(acc[i][j] + bb, 0.f);
            }
        }
    }
}

// ---------------- K2: hmean + g + gz --------------------------------------
__global__ __launch_bounds__(128) void k2_gz(const float* __restrict__ giw,
                                             const float* __restrict__ gib,
                                             const float* __restrict__ c3w,
                                             const float* __restrict__ c3b) {
    const int b = blockIdx.x, tid = threadIdx.x;
    const int w = tid >> 5, lane = tid & 31;
    __shared__ float shm[100];
    __shared__ float sg[100];
    for (int f = w; f < 100; f += 4) {
        const float* hp = &g_h[(b * F_ + f) * L_];
        float s = 0.f;
        for (int l = lane; l < L_; l += 32) s += hp[l];
#pragma unroll
        for (int o = 16; o > 0; o >>= 1) s += __shfl_down_sync(0xffffffffu, s, o);
        if (lane == 0) shm[f] = s * (1.f / (float)L_);
    }
    __syncthreads();
    if (tid < 100) {
        float a = gib[tid];
        const float* wr = &giw[tid * 100];
        for (int f = 0; f < 100; f++) a = fmaf(wr[f], shm[f], a);
        sg[tid] = fmaxf(a, 0.f);
    }
    __syncthreads();
    if (tid < 100) {
        float a = c3b[tid];
        const float* wr = &c3w[tid * 200];
        for (int h = 0; h < 100; h++) a = fmaf(wr[h], sg[h], a);
        g_gz[b * F_ + tid] = a;
    }
}

// ---------------- K3: conv2 -> li -> conv3(loc)+conv4 -> logits -----------
__global__ __launch_bounds__(256) void k3_main(const float* __restrict__ b2,
                                               const float* __restrict__ lb,
                                               const float* __restrict__ w3,
                                               const float* __restrict__ c4w,
                                               const float* __restrict__ c4b) {
    extern __shared__ float smem[];
    const int ST = 148;
    float* sA = smem;                 // [100][148]  (h tile, later loc)
    float* sB = smem + 100 * ST;      // [100][148]  (h2 tile)
    float* sW = smem + 200 * ST;      // [100*128], reused for W3loc [100][100]
    __shared__ float sGz[100];
    __shared__ float sRed[256];

    const int b = blockIdx.y;
    const int l0 = blockIdx.x * LT_;
    const int tid = threadIdx.x;

    for (int idx = tid; idx < 200 * ST; idx += 256) smem[idx] = 0.f;
    __syncthreads();
    // load h tile with halo 2: sA[e][c] = h[b][e][l0-2+c], c in [0,132)
    for (int idx = tid; idx < 100 * 132; idx += 256) {
        int e = idx / 132;
        int c = idx - e * 132;
        int l = l0 - 2 + c;
        if ((unsigned)l < (unsigned)L_) sA[e * ST + c] = g_h[(b * F_ + e) * L_ + l];
    }
    if (tid < 100) sGz[tid] = g_gz[b * F_ + tid];
    __syncthreads();

    const int tx = tid & 15, ty = tid >> 4;

    // conv2: 130 output columns (halo 1 for li), TN=9
    {
        float acc[8][9];
        conv_core<9>(g_W2t, sA, ST, sW, acc);
#pragma unroll
        for (int i = 0; i < 8; i++) {
            int f = ty * 8 + i;
            if (f < 100) {
                float bb = b2[f];
#pragma unroll
                for (int j = 0; j < 9; j++) {
                    int n = tx + j * 16;
                    if (n < 130) sB[f * ST + n] = fmaxf(acc[i][j] + bb, 0.f);
                }
            }
        }
    }
    __syncthreads();
    // li: 128 output columns -> loc into sA
    {
        float acc[8][8];
        conv_core<8>(g_WLt, sB, ST, sW, acc);
#pragma unroll
        for (int i = 0; i < 8; i++) {
            int f = ty * 8 + i;
            if (f < 100) {
                float bb = lb[f];
#pragma unroll
                for (int j = 0; j < 8; j++) sA[f * ST + tx + j * 16] = fmaxf(acc[i][j] + bb, 0.f);
            }
        }
    }
    __syncthreads();
    // stage loc-half of conv3 weights: sW[f*100+h] = w3[f][100+h]
    for (int idx = tid; idx < 100 * 100; idx += 256) {
        int f = idx / 100;
        int h = idx - f * 100;
        sW[idx] = w3[f * 200 + 100 + h];
    }
    __syncthreads();

    // conv3(loc)+relu then conv4 dot, 2 threads per column (f split 50/50)
    const float c4bias = c4b[0];
    const int c = tid & 127;
    const int half = tid >> 7;
    float r = 0.f;
    for (int fc = 0; fc < 5; fc++) {
        int fbase = half * 50 + fc * 10;
        float a10[10];
#pragma unroll
        for (int q = 0; q < 10; q++) a10[q] = sGz[fbase + q];
        for (int h = 0; h < 100; h++) {
            float lv = sA[h * ST + c];
            const float* wr = &sW[fbase * 100 + h];
#pragma unroll
            for (int q = 0; q < 10; q++) a10[q] = fmaf(wr[q * 100], lv, a10[q]);
        }
#pragma unroll
        for (int q = 0; q < 10; q++) r += c4w[fbase + q] * fmaxf(a10[q], 0.f);
    }
    sRed[tid] = r;
    __syncthreads();
    if (tid < 128) g_logits[b * L_ + l0 + tid] = sRed[tid] + sRed[tid + 128] + c4bias;
}

// ---------------- block reduction helpers (256 threads) -------------------
__device__ __forceinline__ float bmax256(float v, float* sred) {
#pragma unroll
    for (int o = 16; o > 0; o >>= 1) v = fmaxf(v, __shfl_xor_sync(0xffffffffu, v, o));
    int w = threadIdx.x >> 5;
    if ((threadIdx.x & 31) == 0) sred[w] = v;
    __syncthreads();
    if (threadIdx.x == 0) {
        float t = sred[0];
#pragma unroll
        for (int i = 1; i < 8; i++) t = fmaxf(t, sred[i]);
        sred[0] = t;
    }
    __syncthreads();
    float r = sred[0];
    __syncthreads();
    return r;
}
__device__ __forceinline__ float bsum256(float v, float* sred) {
#pragma unroll
    for (int o = 16; o > 0; o >>= 1) v += __shfl_xor_sync(0xffffffffu, v, o);
    int w = threadIdx.x >> 5;
    if ((threadIdx.x & 31) == 0) sred[w] = v;
    __syncthreads();
    if (threadIdx.x == 0) {
        float t = sred[0];
#pragma unroll
        for (int i = 1; i < 8; i++) t += sred[i];
        sred[0] = t;
    }
    __syncthreads();
    float r = sred[0];
    __syncthreads();
    return r;
}

// ---------------- K4: Gumbel softmax over L, max over K -> csamples -------
__global__ __launch_bounds__(256) void k4_gumbel(const float* __restrict__ u,
                                                 float* __restrict__ cs_out) {
    const int b = blockIdx.x, tid = threadIdx.x;
    __shared__ float slog[L_];
    __shared__ float sred[8];
    const float EPS = 1.1920929e-07f;
    const float invT = 1.0f / 0.3f;

    for (int l = tid; l < L_; l += 256) slog[l] = g_logits[b * L_ + l];
    __syncthreads();

    float cs0 = 0.f, cs1 = 0.f;   // running max over k for this thread's 2 columns
    for (int k = 0; k < KK_; k++) {
        const float* ub = u + (b * KK_ + k) * L_;
        float u0 = ub[tid], u1 = ub[tid + 256];
        u0 = fminf(fmaxf(u0, EPS), 1.0f - EPS);
        u1 = fminf(fmaxf(u1, EPS), 1.0f - EPS);
        float nv0 = (-logf(-logf(u0)) + slog[tid]) * invT;
        float nv1 = (-logf(-logf(u1)) + slog[tid + 256]) * invT;
        float m = bmax256(fmaxf(nv0, nv1), sred);
        float e0 = expf(nv0 - m), e1 = expf(nv1 - m);
        float s = bsum256(e0 + e1, sred);
        float rs = 1.f / s;
        cs0 = fmaxf(cs0, e0 * rs);
        cs1 = fmaxf(cs1, e1 * rs);
    }
    cs_out[b * L_ + tid] = cs0;
    cs_out[b * L_ + tid + 256] = cs1;
}

// ---------------- K5: weighted pooling + MLP + sigmoid --------------------
__global__ __launch_bounds__(128) void k5_final(const int* __restrict__ x,
                                                const float* __restrict__ emb,
                                                const float* __restrict__ f1w,
                                                const float* __restrict__ f1b,
                                                const float* __restrict__ hw,
                                                const float* __restrict__ hb,
                                                const float* __restrict__ cs,
                                                float* __restrict__ out) {
    const int b = blockIdx.x, tid = threadIdx.x;
    __shared__ float scs[L_];
    __shared__ int sx[L_];
    __shared__ float spool[100];
    __shared__ float sh[100];
    __shared__ float sred[4];
    for (int l = tid; l < L_; l += 128) {
        scs[l] = cs[b * L_ + l];
        sx[l] = x[b * L_ + l];
    }
    __syncthreads();
    if (tid < 100) {
        float acc = 0.f;
        for (int l = 0; l < L_; l += 8) {
            float p[8];
#pragma unroll
            for (int q = 0; q < 8; q++) p[q] = emb[sx[l + q] * E_ + tid];
#pragma unroll
            for (int q = 0; q < 8; q++) acc = fmaf(scs[l + q], p[q], acc);
        }
        spool[tid] = acc * (1.f / (float)L_);
    }
    __syncthreads();
    if (tid < 100) {
        float a = f1b[tid];
        const float* wr = &f1w[tid * 100];
        for (int e = 0; e < 100; e++) a = fmaf(wr[e], spool[e], a);
        sh[tid] = fmaxf(a, 0.f);
    }
    __syncthreads();
    float hv = (tid < 100) ? hw[tid] * sh[tid] : 0.f;
#pragma unroll
    for (int o = 16; o > 0; o >>= 1) hv += __shfl_xor_sync(0xffffffffu, hv, o);
    if ((tid & 31) == 0) sred[tid >> 5] = hv;
    __syncthreads();
    if (tid == 0) {
        float t = sred[0] + sred[1] + sred[2] + sred[3] + hb[0];
        out[b] = 1.f / (1.f + expf(-t));
    }
}

// ---------------- launch ---------------------------------------------------
extern "C" void kernel_launch(void* const* d_in, const int* in_sizes, int n_in,
                              void* d_out, int out_size) {
    const int*   x   = (const int*)  d_in[0];
    const float* u   = (const float*)d_in[1];
    const float* emb = (const float*)d_in[2];
    const float* c1w = (const float*)d_in[3];
    const float* c1b = (const float*)d_in[4];
    const float* giw = (const float*)d_in[5];
    const float* gib = (const float*)d_in[6];
    const float* c2w = (const float*)d_in[7];
    const float* c2b = (const float*)d_in[8];
    const float* liw = (const float*)d_in[9];
    const float* lib = (const float*)d_in[10];
    const float* c3w = (const float*)d_in[11];
    const float* c3b = (const float*)d_in[12];
    const float* c4w = (const float*)d_in[13];
    const float* c4b = (const float*)d_in[14];
    const float* f1w = (const float*)d_in[15];
    const float* f1b = (const float*)d_in[16];
    const float* hw  = (const float*)d_in[17];
    const float* hb  = (const float*)d_in[18];

    float* out = (float*)d_out;          // [B,1] first
    float* cs  = out + B_;               // then csamples [B,L]

    const int SMEM1 = (100 * 132 + 100 * 128) * 4;   // 104 KB
    const int SMEM3 = (200 * 148 + 100 * 128) * 4;   // 169.6 KB
    cudaFuncSetAttribute(k1_conv1, cudaFuncAttributeMaxDynamicSharedMemorySize, SMEM1);
    cudaFuncSetAttribute(k3_main, cudaFuncAttributeMaxDynamicSharedMemorySize, SMEM3);

    k0_prep<<<(3 * 100 * 128 + 255) / 256, 256>>>(c1w, c2w, liw);
    k1_conv1<<<dim3(L_ / LT_, B_), 256, SMEM1>>>(x, emb, c1b);
    k2_gz<<<B_, 128>>>(giw, gib, c3w, c3b);
    k3_main<<<dim3(L_ / LT_, B_), 256, SMEM3>>>(c2b, lib, c3w, c4w, c4b);
    k4_gumbel<<<B_, 256>>>(u, cs);
    k5_final<<<B_, 128>>>(x, emb, f1w, f1b, hw, hb, cs, out);
}

// round 2
// speedup vs baseline: 1.0247x; 1.0247x over previous
#include <cuda_runtime.h>
#include <math.h>

#define B_   512
#define L_   512
#define E_   100
#define F_   100
#define H_   100
#define KK_  10

// ---------------- scratch (device globals; no allocations) ----------------
__device__ float g_h[B_ * F_ * L_];          // 104.8 MB  h = relu(conv1)
__device__ float g_logits[B_ * L_];          // 1 MB
__device__ float g_gz[B_ * F_];              // per-batch global half of conv3 (+bias)
__device__ float g_W1t[3 * 100 * 128];       // transposed/padded conv weights [dx][e][f]
__device__ float g_W2t[3 * 100 * 128];
__device__ float g_WLt[3 * 100 * 128];

// ---------------- K0: weight transpose [F][E][3] -> [3][E][128(F pad)] ----
__global__ void k0_prep(const float* __restrict__ w1, const float* __restrict__ w2,
                        const float* __restrict__ wl) {
    int idx = blockIdx.x * 256 + threadIdx.x;
    if (idx >= 3 * 100 * 128) return;
    int dx = idx / (100 * 128);
    int rem = idx - dx * (100 * 128);
    int e = rem >> 7;
    int f = rem & 127;
    float v1 = 0.f, v2 = 0.f, v3 = 0.f;
    if (f < 100) {
        int src = f * 300 + e * 3 + dx;
        v1 = w1[src]; v2 = w2[src]; v3 = wl[src];
    }
    g_W1t[idx] = v1; g_W2t[idx] = v2; g_WLt[idx] = v3;
}

// ---------------- shared conv GEMM core (chunked weight staging) -----------
// out[f][n] = sum_{e<100,dx<3} W[dx][e][f] * sIn[e][n+dx], f = ty*8+i, n = tx+j*16.
// Weights staged in sW as [50][128] chunks (CH=50) to keep smem small.
template <int TN>
__device__ __forceinline__ void conv_core(const float* __restrict__ Wt,
                                          const float* sIn, int inStride,
                                          float* sW, float acc[8][TN]) {
    const int tid = threadIdx.x;
    const int tx = tid & 15;
    const int ty = tid >> 4;
#pragma unroll
    for (int i = 0; i < 8; i++)
#pragma unroll
        for (int j = 0; j < TN; j++) acc[i][j] = 0.f;

    for (int dx = 0; dx < 3; dx++) {
        for (int ch = 0; ch < 2; ch++) {
            __syncthreads();   // protect sW before overwrite
            for (int idx = tid; idx < 50 * 128; idx += 256)
                sW[idx] = Wt[dx * 100 * 128 + ch * 50 * 128 + idx];
            __syncthreads();
#pragma unroll 2
            for (int e = 0; e < 50; e++) {
                const float4* w4 = reinterpret_cast<const float4*>(&sW[e * 128 + ty * 8]);
                float4 a0 = w4[0], a1 = w4[1];
                float a[8] = {a0.x, a0.y, a0.z, a0.w, a1.x, a1.y, a1.z, a1.w};
                const float* xrow = &sIn[(ch * 50 + e) * inStride + tx + dx];
                float bfr[TN];
#pragma unroll
                for (int j = 0; j < TN; j++) bfr[j] = xrow[j * 16];
#pragma unroll
                for (int i = 0; i < 8; i++)
#pragma unroll
                    for (int j = 0; j < TN; j++)
                        acc[i][j] = fmaf(a[i], bfr[j], acc[i][j]);
            }
        }
    }
}

// ---------------- K1: embedding gather + conv1 -> g_h (tile 128) ----------
__global__ __launch_bounds__(256, 2) void k1_conv1(const int* __restrict__ x,
                                                   const float* __restrict__ emb,
                                                   const float* __restrict__ b1) {
    extern __shared__ float smem[];
    float* sE = smem;                 // [100][132]
    float* sW = smem + 100 * 132;     // [50*128]
    const int b = blockIdx.y;
    const int l0 = blockIdx.x * 128;
    const int tid = threadIdx.x;

    // sE[e][c] = emb[x[b][l0-1+c]][e], c in [0,130); cols 130,131 zero
    for (int idx = tid; idx < 130 * 100; idx += 256) {
        int c = idx / 100;
        int e = idx - c * 100;
        int l = l0 - 1 + c;
        float v = 0.f;
        if ((unsigned)l < (unsigned)L_) {
            int row = x[b * L_ + l];
            v = emb[row * E_ + e];
        }
        sE[e * 132 + c] = v;
    }
    for (int e = tid; e < 100; e += 256) { sE[e * 132 + 130] = 0.f; sE[e * 132 + 131] = 0.f; }
    __syncthreads();

    float acc[8][8];
    conv_core<8>(g_W1t, sE, 132, sW, acc);

    const int tx = tid & 15, ty = tid >> 4;
#pragma unroll
    for (int i = 0; i < 8; i++) {
        int f = ty * 8 + i;
        if (f < 100) {
            float bb = b1[f];
            float* dst = &g_h[(b * F_ + f) * L_ + l0];
#pragma unroll
            for (int j = 0; j < 8; j++) {
                int n = tx + j * 16;
                dst[n] = fmaxf(acc[i][j] + bb, 0.f);
            }
        }
    }
}

// ---------------- K2: hmean + g + gz --------------------------------------
__global__ __launch_bounds__(128) void k2_gz(const float* __restrict__ giw,
                                             const float* __restrict__ gib,
                                             const float* __restrict__ c3w,
                                             const float* __restrict__ c3b) {
    const int b = blockIdx.x, tid = threadIdx.x;
    const int w = tid >> 5, lane = tid & 31;
    __shared__ float shm[100];
    __shared__ float sg[100];
    for (int f = w; f < 100; f += 4) {
        const float* hp = &g_h[(b * F_ + f) * L_];
        float s = 0.f;
        for (int l = lane; l < L_; l += 32) s += hp[l];
#pragma unroll
        for (int o = 16; o > 0; o >>= 1) s += __shfl_down_sync(0xffffffffu, s, o);
        if (lane == 0) shm[f] = s * (1.f / (float)L_);
    }
    __syncthreads();
    if (tid < 100) {
        float a = gib[tid];
        const float* wr = &giw[tid * 100];
        for (int f = 0; f < 100; f++) a = fmaf(wr[f], shm[f], a);
        sg[tid] = fmaxf(a, 0.f);
    }
    __syncthreads();
    if (tid < 100) {
        float a = c3b[tid];
        const float* wr = &c3w[tid * 200];
        for (int h = 0; h < 100; h++) a = fmaf(wr[h], sg[h], a);
        g_gz[b * F_ + tid] = a;
    }
}

// ---------------- K3: conv2 -> li -> conv3(loc)+conv4 -> logits (tile 64) --
__global__ __launch_bounds__(256, 2) void k3_main(const float* __restrict__ b2,
                                                  const float* __restrict__ lb,
                                                  const float* __restrict__ w3,
                                                  const float* __restrict__ c4w,
                                                  const float* __restrict__ c4b) {
    extern __shared__ float smem[];
    const int ST = 84;
    float* sA = smem;                 // [100][84]  (h tile w/ halo 2, later loc)
    float* sB = smem + 100 * ST;      // [100][84]  (conv2 output, 66 cols)
    float* sW = smem + 200 * ST;      // [10000]: conv chunks [50][128] / W3loc [100][100]
    __shared__ float sGz[100];
    __shared__ float sRed[256];

    const int b = blockIdx.y;
    const int l0 = blockIdx.x * 64;
    const int tid = threadIdx.x;

    for (int idx = tid; idx < 200 * ST; idx += 256) smem[idx] = 0.f;
    __syncthreads();
    // h tile with halo 2: sA[e][c] = h[b][e][l0-2+c], c in [0,68)
    for (int idx = tid; idx < 100 * 68; idx += 256) {
        int e = idx / 68;
        int c = idx - e * 68;
        int l = l0 - 2 + c;
        if ((unsigned)l < (unsigned)L_) sA[e * ST + c] = g_h[(b * F_ + e) * L_ + l];
    }
    if (tid < 100) sGz[tid] = g_gz[b * F_ + tid];
    __syncthreads();

    const int tx = tid & 15, ty = tid >> 4;

    // conv2: 66 output columns (n -> l = l0-1+n), TN=5 masked
    {
        float acc[8][5];
        conv_core<5>(g_W2t, sA, ST, sW, acc);
        __syncthreads();
#pragma unroll
        for (int i = 0; i < 8; i++) {
            int f = ty * 8 + i;
            if (f < 100) {
                float bb = b2[f];
#pragma unroll
                for (int j = 0; j < 5; j++) {
                    int n = tx + j * 16;
                    if (n < 66) sB[f * ST + n] = fmaxf(acc[i][j] + bb, 0.f);
                }
            }
        }
    }
    __syncthreads();
    // li: 64 output columns (m -> l = l0+m) -> loc into sA
    {
        float acc[8][4];
        conv_core<4>(g_WLt, sB, ST, sW, acc);
        __syncthreads();
#pragma unroll
        for (int i = 0; i < 8; i++) {
            int f = ty * 8 + i;
            if (f < 100) {
                float bb = lb[f];
#pragma unroll
                for (int j = 0; j < 4; j++) sA[f * ST + tx + j * 16] = fmaxf(acc[i][j] + bb, 0.f);
            }
        }
    }
    __syncthreads();
    // stage loc-half of conv3 weights: sW[f*100+h] = w3[f][100+h]
    for (int idx = tid; idx < 100 * 100; idx += 256) {
        int f = idx / 100;
        int h = idx - f * 100;
        sW[idx] = w3[f * 200 + 100 + h];
    }
    __syncthreads();

    // conv3(loc)+relu then conv4 dot; 4 threads per column (25 f-rows each)
    const float c4bias = c4b[0];
    const int c = tid & 63;
    const int part = tid >> 6;
    float r = 0.f;
#pragma unroll
    for (int fc = 0; fc < 5; fc++) {
        int fbase = part * 25 + fc * 5;
        float a5[5];
#pragma unroll
        for (int q = 0; q < 5; q++) a5[q] = sGz[fbase + q];
        for (int h = 0; h < 100; h++) {
            float lv = sA[h * ST + c];
            const float* wr = &sW[fbase * 100 + h];
#pragma unroll
            for (int q = 0; q < 5; q++) a5[q] = fmaf(wr[q * 100], lv, a5[q]);
        }
#pragma unroll
        for (int q = 0; q < 5; q++) r += c4w[fbase + q] * fmaxf(a5[q], 0.f);
    }
    sRed[tid] = r;
    __syncthreads();
    if (tid < 64)
        g_logits[b * L_ + l0 + tid] =
            sRed[tid] + sRed[tid + 64] + sRed[tid + 128] + sRed[tid + 192] + c4bias;
}

// ---------------- block reduction helpers (256 threads) -------------------
__device__ __forceinline__ float bmax256(float v, float* sred) {
#pragma unroll
    for (int o = 16; o > 0; o >>= 1) v = fmaxf(v, __shfl_xor_sync(0xffffffffu, v, o));
    int w = threadIdx.x >> 5;
    if ((threadIdx.x & 31) == 0) sred[w] = v;
    __syncthreads();
    if (threadIdx.x == 0) {
        float t = sred[0];
#pragma unroll
        for (int i = 1; i < 8; i++) t = fmaxf(t, sred[i]);
        sred[0] = t;
    }
    __syncthreads();
    float r = sred[0];
    __syncthreads();
    return r;
}
__device__ __forceinline__ float bsum256(float v, float* sred) {
#pragma unroll
    for (int o = 16; o > 0; o >>= 1) v += __shfl_xor_sync(0xffffffffu, v, o);
    int w = threadIdx.x >> 5;
    if ((threadIdx.x & 31) == 0) sred[w] = v;
    __syncthreads();
    if (threadIdx.x == 0) {
        float t = sred[0];
#pragma unroll
        for (int i = 1; i < 8; i++) t += sred[i];
        sred[0] = t;
    }
    __syncthreads();
    float r = sred[0];
    __syncthreads();
    return r;
}

// ---------------- K4: csamples init + per-(b,k) softmax w/ atomic max -----
__global__ __launch_bounds__(256) void k4_init(float* __restrict__ cs) {
    int i = blockIdx.x * 256 + threadIdx.x;
    if (i < B_ * L_) cs[i] = 0.f;
}
__global__ __launch_bounds__(256) void k4_gumbel(const float* __restrict__ u,
                                                 float* __restrict__ cs_out) {
    const int k = blockIdx.x, b = blockIdx.y, tid = threadIdx.x;
    __shared__ float sred[8];
    const float EPS = 1.1920929e-07f;
    const float invT = 1.0f / 0.3f;

    const float* lg = g_logits + b * L_;
    const float* ub = u + (b * KK_ + k) * L_;
    float u0 = ub[tid], u1 = ub[tid + 256];
    u0 = fminf(fmaxf(u0, EPS), 1.0f - EPS);
    u1 = fminf(fmaxf(u1, EPS), 1.0f - EPS);
    float nv0 = (-logf(-logf(u0)) + lg[tid]) * invT;
    float nv1 = (-logf(-logf(u1)) + lg[tid + 256]) * invT;
    float m = bmax256(fmaxf(nv0, nv1), sred);
    float e0 = expf(nv0 - m), e1 = expf(nv1 - m);
    float s = bsum256(e0 + e1, sred);
    float rs = 1.f / s;
    // softmax values are >= 0, so int-ordered compare == float compare
    atomicMax((int*)&cs_out[b * L_ + tid], __float_as_int(e0 * rs));
    atomicMax((int*)&cs_out[b * L_ + tid + 256], __float_as_int(e1 * rs));
}

// ---------------- K5: weighted pooling + MLP + sigmoid --------------------
__global__ __launch_bounds__(128) void k5_final(const int* __restrict__ x,
                                                const float* __restrict__ emb,
                                                const float* __restrict__ f1w,
                                                const float* __restrict__ f1b,
                                                const float* __restrict__ hw,
                                                const float* __restrict__ hb,
                                                const float* __restrict__ cs,
                                                float* __restrict__ out) {
    const int b = blockIdx.x, tid = threadIdx.x;
    __shared__ float scs[L_];
    __shared__ int sx[L_];
    __shared__ float spool[100];
    __shared__ float sh[100];
    __shared__ float sred[4];
    for (int l = tid; l < L_; l += 128) {
        scs[l] = cs[b * L_ + l];
        sx[l] = x[b * L_ + l];
    }
    __syncthreads();
    if (tid < 100) {
        float acc = 0.f;
        for (int l = 0; l < L_; l += 8) {
            float p[8];
#pragma unroll
            for (int q = 0; q < 8; q++) p[q] = emb[sx[l + q] * E_ + tid];
#pragma unroll
            for (int q = 0; q < 8; q++) acc = fmaf(scs[l + q], p[q], acc);
        }
        spool[tid] = acc * (1.f / (float)L_);
    }
    __syncthreads();
    if (tid < 100) {
        float a = f1b[tid];
        const float* wr = &f1w[tid * 100];
        for (int e = 0; e < 100; e++) a = fmaf(wr[e], spool[e], a);
        sh[tid] = fmaxf(a, 0.f);
    }
    __syncthreads();
    float hv = (tid < 100) ? hw[tid] * sh[tid] : 0.f;
#pragma unroll
    for (int o = 16; o > 0; o >>= 1) hv += __shfl_xor_sync(0xffffffffu, hv, o);
    if ((tid & 31) == 0) sred[tid >> 5] = hv;
    __syncthreads();
    if (tid == 0) {
        float t = sred[0] + sred[1] + sred[2] + sred[3] + hb[0];
        out[b] = 1.f / (1.f + expf(-t));
    }
}

// ---------------- launch ---------------------------------------------------
extern "C" void kernel_launch(void* const* d_in, const int* in_sizes, int n_in,
                              void* d_out, int out_size) {
    const int*   x   = (const int*)  d_in[0];
    const float* u   = (const float*)d_in[1];
    const float* emb = (const float*)d_in[2];
    const float* c1w = (const float*)d_in[3];
    const float* c1b = (const float*)d_in[4];
    const float* giw = (const float*)d_in[5];
    const float* gib = (const float*)d_in[6];
    const float* c2w = (const float*)d_in[7];
    const float* c2b = (const float*)d_in[8];
    const float* liw = (const float*)d_in[9];
    const float* lib = (const float*)d_in[10];
    const float* c3w = (const float*)d_in[11];
    const float* c3b = (const float*)d_in[12];
    const float* c4w = (const float*)d_in[13];
    const float* c4b = (const float*)d_in[14];
    const float* f1w = (const float*)d_in[15];
    const float* f1b = (const float*)d_in[16];
    const float* hw  = (const float*)d_in[17];
    const float* hb  = (const float*)d_in[18];

    float* out = (float*)d_out;          // [B,1] first
    float* cs  = out + B_;               // then csamples [B,L]

    const int SMEM1 = (100 * 132 + 50 * 128) * 4;    // 78.4 KB -> 2 CTAs/SM
    const int SMEM3 = (200 * 84 + 10000) * 4;        // 107.2 KB -> 2 CTAs/SM
    cudaFuncSetAttribute(k1_conv1, cudaFuncAttributeMaxDynamicSharedMemorySize, SMEM1);
    cudaFuncSetAttribute(k3_main, cudaFuncAttributeMaxDynamicSharedMemorySize, SMEM3);

    k0_prep<<<(3 * 100 * 128 + 255) / 256, 256>>>(c1w, c2w, liw);
    k1_conv1<<<dim3(L_ / 128, B_), 256, SMEM1>>>(x, emb, c1b);
    k2_gz<<<B_, 128>>>(giw, gib, c3w, c3b);
    k3_main<<<dim3(L_ / 64, B_), 256, SMEM3>>>(c2b, lib, c3w, c4w, c4b);
    k4_init<<<(B_ * L_ + 255) / 256, 256>>>(cs);
    k4_gumbel<<<dim3(KK_, B_), 256>>>(u, cs);
    k5_final<<<B_, 128>>>(x, emb, f1w, f1b, hw, hb, cs, out);
}

// round 3
// speedup vs baseline: 1.0250x; 1.0003x over previous
#include <cuda_runtime.h>
#include <math.h>

#define B_   512
#define L_   512
#define E_   100
#define F_   100
#define H_   100
#define KK_  10

// ---------------- scratch (device globals; no allocations) ----------------
__device__ float g_h[B_ * F_ * L_];          // 104.8 MB  h = relu(conv1)
__device__ float g_logits[B_ * L_];          // 1 MB
__device__ float g_gz[B_ * F_];              // per-batch global half of conv3 (+bias)
__device__ float g_W1t[3 * 100 * 128];       // transposed/padded conv weights [dx][e][f]
__device__ float g_W2t[3 * 100 * 128];
__device__ float g_WLt[3 * 100 * 128];

// ---------------- K0: weight transpose [F][E][3] -> [3][E][128(F pad)] ----
__global__ void k0_prep(const float* __restrict__ w1, const float* __restrict__ w2,
                        const float* __restrict__ wl) {
    int idx = blockIdx.x * 256 + threadIdx.x;
    if (idx >= 3 * 100 * 128) return;
    int dx = idx / (100 * 128);
    int rem = idx - dx * (100 * 128);
    int e = rem >> 7;
    int f = rem & 127;
    float v1 = 0.f, v2 = 0.f, v3 = 0.f;
    if (f < 100) {
        int src = f * 300 + e * 3 + dx;
        v1 = w1[src]; v2 = w2[src]; v3 = wl[src];
    }
    g_W1t[idx] = v1; g_W2t[idx] = v2; g_WLt[idx] = v3;
}

// ---------------- shared conv GEMM core (chunked weight staging) -----------
// out[f][n] = sum_{e<100,dx<3} W[dx][e][f] * sIn[e][n+dx], f = ty*8+i, n = tx+j*16.
// Weights staged in sW as [50][128] chunks (CH=50) to keep smem small.
template <int TN>
__device__ __forceinline__ void conv_core(const float* __restrict__ Wt,
                                          const float* sIn, int inStride,
                                          float* sW, float acc[8][TN]) {
    const int tid = threadIdx.x;
    const int tx = tid & 15;
    const int ty = tid >> 4;
#pragma unroll
    for (int i = 0; i < 8; i++)
#pragma unroll
        for (int j = 0; j < TN; j++) acc[i][j] = 0.f;

    for (int dx = 0; dx < 3; dx++) {
        for (int ch = 0; ch < 2; ch++) {
            __syncthreads();   // protect sW before overwrite
            for (int idx = tid; idx < 50 * 128; idx += 256)
                sW[idx] = Wt[dx * 100 * 128 + ch * 50 * 128 + idx];
            __syncthreads();
#pragma unroll 2
            for (int e = 0; e < 50; e++) {
                const float4* w4 = reinterpret_cast<const float4*>(&sW[e * 128 + ty * 8]);
                float4 a0 = w4[0], a1 = w4[1];
                float a[8] = {a0.x, a0.y, a0.z, a0.w, a1.x, a1.y, a1.z, a1.w};
                const float* xrow = &sIn[(ch * 50 + e) * inStride + tx + dx];
                float bfr[TN];
#pragma unroll
                for (int j = 0; j < TN; j++) bfr[j] = xrow[j * 16];
#pragma unroll
                for (int i = 0; i < 8; i++)
#pragma unroll
                    for (int j = 0; j < TN; j++)
                        acc[i][j] = fmaf(a[i], bfr[j], acc[i][j]);
            }
        }
    }
}

// ---------------- K1: embedding gather + conv1 -> g_h (tile 128) ----------
__global__ __launch_bounds__(256, 2) void k1_conv1(const int* __restrict__ x,
                                                   const float* __restrict__ emb,
                                                   const float* __restrict__ b1) {
    extern __shared__ float smem[];
    float* sE = smem;                 // [100][132]
    float* sW = smem + 100 * 132;     // [50*128]
    const int b = blockIdx.y;
    const int l0 = blockIdx.x * 128;
    const int tid = threadIdx.x;

    // sE[e][c] = emb[x[b][l0-1+c]][e], c in [0,130); cols 130,131 zero
    for (int idx = tid; idx < 130 * 100; idx += 256) {
        int c = idx / 100;
        int e = idx - c * 100;
        int l = l0 - 1 + c;
        float v = 0.f;
        if ((unsigned)l < (unsigned)L_) {
            int row = x[b * L_ + l];
            v = emb[row * E_ + e];
        }
        sE[e * 132 + c] = v;
    }
    for (int e = tid; e < 100; e += 256) { sE[e * 132 + 130] = 0.f; sE[e * 132 + 131] = 0.f; }
    __syncthreads();

    float acc[8][8];
    conv_core<8>(g_W1t, sE, 132, sW, acc);

    const int tx = tid & 15, ty = tid >> 4;
#pragma unroll
    for (int i = 0; i < 8; i++) {
        int f = ty * 8 + i;
        if (f < 100) {
            float bb = b1[f];
            float* dst = &g_h[(b * F_ + f) * L_ + l0];
#pragma unroll
            for (int j = 0; j < 8; j++) {
                int n = tx + j * 16;
                dst[n] = fmaxf(acc[i][j] + bb, 0.f);
            }
        }
    }
}

// ---------------- K2: hmean + g + gz --------------------------------------
__global__ __launch_bounds__(128) void k2_gz(const float* __restrict__ giw,
                                             const float* __restrict__ gib,
                                             const float* __restrict__ c3w,
                                             const float* __restrict__ c3b) {
    const int b = blockIdx.x, tid = threadIdx.x;
    const int w = tid >> 5, lane = tid & 31;
    __shared__ float shm[100];
    __shared__ float sg[100];
    for (int f = w; f < 100; f += 4) {
        const float* hp = &g_h[(b * F_ + f) * L_];
        float s = 0.f;
        for (int l = lane; l < L_; l += 32) s += hp[l];
#pragma unroll
        for (int o = 16; o > 0; o >>= 1) s += __shfl_down_sync(0xffffffffu, s, o);
        if (lane == 0) shm[f] = s * (1.f / (float)L_);
    }
    __syncthreads();
    if (tid < 100) {
        float a = gib[tid];
        const float* wr = &giw[tid * 100];
        for (int f = 0; f < 100; f++) a = fmaf(wr[f], shm[f], a);
        sg[tid] = fmaxf(a, 0.f);
    }
    __syncthreads();
    if (tid < 100) {
        float a = c3b[tid];
        const float* wr = &c3w[tid * 200];
        for (int h = 0; h < 100; h++) a = fmaf(wr[h], sg[h], a);
        g_gz[b * F_ + tid] = a;
    }
}

// ---------------- K3: conv2 -> li -> conv3(loc)+conv4 -> logits (tile 64) --
__global__ __launch_bounds__(256, 2) void k3_main(const float* __restrict__ b2,
                                                  const float* __restrict__ lb,
                                                  const float* __restrict__ w3,
                                                  const float* __restrict__ c4w,
                                                  const float* __restrict__ c4b) {
    extern __shared__ float smem[];
    const int ST = 84;
    float* sA = smem;                 // [100][84]  (h tile w/ halo 2, later loc)
    float* sB = smem + 100 * ST;      // [100][84]  (conv2 output, 66 cols)
    float* sW = smem + 200 * ST;      // [10000]: conv chunks [50][128] / W3loc [100][100]
    __shared__ float sGz[100];
    __shared__ float sRed[256];

    const int b = blockIdx.y;
    const int l0 = blockIdx.x * 64;
    const int tid = threadIdx.x;

    for (int idx = tid; idx < 200 * ST; idx += 256) smem[idx] = 0.f;
    __syncthreads();
    // h tile with halo 2: sA[e][c] = h[b][e][l0-2+c], c in [0,68)
    for (int idx = tid; idx < 100 * 68; idx += 256) {
        int e = idx / 68;
        int c = idx - e * 68;
        int l = l0 - 2 + c;
        if ((unsigned)l < (unsigned)L_) sA[e * ST + c] = g_h[(b * F_ + e) * L_ + l];
    }
    if (tid < 100) sGz[tid] = g_gz[b * F_ + tid];
    __syncthreads();

    const int tx = tid & 15, ty = tid >> 4;

    // conv2: 66 output columns (n -> l = l0-1+n), TN=5 masked
    {
        float acc[8][5];
        conv_core<5>(g_W2t, sA, ST, sW, acc);
        __syncthreads();
#pragma unroll
        for (int i = 0; i < 8; i++) {
            int f = ty * 8 + i;
            if (f < 100) {
                float bb = b2[f];
#pragma unroll
                for (int j = 0; j < 5; j++) {
                    int n = tx + j * 16;
                    if (n < 66) sB[f * ST + n] = fmaxf(acc[i][j] + bb, 0.f);
                }
            }
        }
    }
    __syncthreads();
    // li: 64 output columns (m -> l = l0+m) -> loc into sA
    {
        float acc[8][4];
        conv_core<4>(g_WLt, sB, ST, sW, acc);
        __syncthreads();
#pragma unroll
        for (int i = 0; i < 8; i++) {
            int f = ty * 8 + i;
            if (f < 100) {
                float bb = lb[f];
#pragma unroll
                for (int j = 0; j < 4; j++) sA[f * ST + tx + j * 16] = fmaxf(acc[i][j] + bb, 0.f);
            }
        }
    }
    __syncthreads();
    // stage loc-half of conv3 weights: sW[f*100+h] = w3[f][100+h]
    for (int idx = tid; idx < 100 * 100; idx += 256) {
        int f = idx / 100;
        int h = idx - f * 100;
        sW[idx] = w3[f * 200 + 100 + h];
    }
    __syncthreads();

    // conv3(loc)+relu then conv4 dot; 4 threads per column (25 f-rows each)
    const float c4bias = c4b[0];
    const int c = tid & 63;
    const int part = tid >> 6;
    float r = 0.f;
#pragma unroll
    for (int fc = 0; fc < 5; fc++) {
        int fbase = part * 25 + fc * 5;
        float a5[5];
#pragma unroll
        for (int q = 0; q < 5; q++) a5[q] = sGz[fbase + q];
        for (int h = 0; h < 100; h++) {
            float lv = sA[h * ST + c];
            const float* wr = &sW[fbase * 100 + h];
#pragma unroll
            for (int q = 0; q < 5; q++) a5[q] = fmaf(wr[q * 100], lv, a5[q]);
        }
#pragma unroll
        for (int q = 0; q < 5; q++) r += c4w[fbase + q] * fmaxf(a5[q], 0.f);
    }
    sRed[tid] = r;
    __syncthreads();
    if (tid < 64)
        g_logits[b * L_ + l0 + tid] =
            sRed[tid] + sRed[tid + 64] + sRed[tid + 128] + sRed[tid + 192] + c4bias;
}

// ---------------- block reduction helpers (256 threads) -------------------
__device__ __forceinline__ float bmax256(float v, float* sred) {
#pragma unroll
    for (int o = 16; o > 0; o >>= 1) v = fmaxf(v, __shfl_xor_sync(0xffffffffu, v, o));
    int w = threadIdx.x >> 5;
    if ((threadIdx.x & 31) == 0) sred[w] = v;
    __syncthreads();
    if (threadIdx.x == 0) {
        float t = sred[0];
#pragma unroll
        for (int i = 1; i < 8; i++) t = fmaxf(t, sred[i]);
        sred[0] = t;
    }
    __syncthreads();
    float r = sred[0];
    __syncthreads();
    return r;
}
__device__ __forceinline__ float bsum256(float v, float* sred) {
#pragma unroll
    for (int o = 16; o > 0; o >>= 1) v += __shfl_xor_sync(0xffffffffu, v, o);
    int w = threadIdx.x >> 5;
    if ((threadIdx.x & 31) == 0) sred[w] = v;
    __syncthreads();
    if (threadIdx.x == 0) {
        float t = sred[0];
#pragma unroll
        for (int i = 1; i < 8; i++) t += sred[i];
        sred[0] = t;
    }
    __syncthreads();
    float r = sred[0];
    __syncthreads();
    return r;
}

// ---------------- K4: csamples init + per-(b,k) softmax w/ atomic max -----
__global__ __launch_bounds__(256) void k4_init(float* __restrict__ cs) {
    int i = blockIdx.x * 256 + threadIdx.x;
    if (i < B_ * L_) cs[i] = 0.f;
}
__global__ __launch_bounds__(256) void k4_gumbel(const float* __restrict__ u,
                                                 float* __restrict__ cs_out) {
    const int k = blockIdx.x, b = blockIdx.y, tid = threadIdx.x;
    __shared__ float sred[8];
    const float EPS = 1.1920929e-07f;
    const float invT = 1.0f / 0.3f;

    const float* lg = g_logits + b * L_;
    const float* ub = u + (b * KK_ + k) * L_;
    float u0 = ub[tid], u1 = ub[tid + 256];
    u0 = fminf(fmaxf(u0, EPS), 1.0f - EPS);
    u1 = fminf(fmaxf(u1, EPS), 1.0f - EPS);
    float nv0 = (-logf(-logf(u0)) + lg[tid]) * invT;
    float nv1 = (-logf(-logf(u1)) + lg[tid + 256]) * invT;
    float m = bmax256(fmaxf(nv0, nv1), sred);
    float e0 = expf(nv0 - m), e1 = expf(nv1 - m);
    float s = bsum256(e0 + e1, sred);
    float rs = 1.f / s;
    // softmax values are >= 0, so int-ordered compare == float compare
    atomicMax((int*)&cs_out[b * L_ + tid], __float_as_int(e0 * rs));
    atomicMax((int*)&cs_out[b * L_ + tid + 256], __float_as_int(e1 * rs));
}

// ---------------- K5: weighted pooling + MLP + sigmoid --------------------
__global__ __launch_bounds__(128) void k5_final(const int* __restrict__ x,
                                                const float* __restrict__ emb,
                                                const float* __restrict__ f1w,
                                                const float* __restrict__ f1b,
                                                const float* __restrict__ hw,
                                                const float* __restrict__ hb,
                                                const float* __restrict__ cs,
                                                float* __restrict__ out) {
    const int b = blockIdx.x, tid = threadIdx.x;
    __shared__ float scs[L_];
    __shared__ int sx[L_];
    __shared__ float spool[100];
    __shared__ float sh[100];
    __shared__ float sred[4];
    for (int l = tid; l < L_; l += 128) {
        scs[l] = cs[b * L_ + l];
        sx[l] = x[b * L_ + l];
    }
    __syncthreads();
    if (tid < 100) {
        float acc = 0.f;
        for (int l = 0; l < L_; l += 8) {
            float p[8];
#pragma unroll
            for (int q = 0; q < 8; q++) p[q] = emb[sx[l + q] * E_ + tid];
#pragma unroll
            for (int q = 0; q < 8; q++) acc = fmaf(scs[l + q], p[q], acc);
        }
        spool[tid] = acc * (1.f / (float)L_);
    }
    __syncthreads();
    if (tid < 100) {
        float a = f1b[tid];
        const float* wr = &f1w[tid * 100];
        for (int e = 0; e < 100; e++) a = fmaf(wr[e], spool[e], a);
        sh[tid] = fmaxf(a, 0.f);
    }
    __syncthreads();
    float hv = (tid < 100) ? hw[tid] * sh[tid] : 0.f;
#pragma unroll
    for (int o = 16; o > 0; o >>= 1) hv += __shfl_xor_sync(0xffffffffu, hv, o);
    if ((tid & 31) == 0) sred[tid >> 5] = hv;
    __syncthreads();
    if (tid == 0) {
        float t = sred[0] + sred[1] + sred[2] + sred[3] + hb[0];
        out[b] = 1.f / (1.f + expf(-t));
    }
}

// ---------------- launch ---------------------------------------------------
extern "C" void kernel_launch(void* const* d_in, const int* in_sizes, int n_in,
                              void* d_out, int out_size) {
    const int*   x   = (const int*)  d_in[0];
    const float* u   = (const float*)d_in[1];
    const float* emb = (const float*)d_in[2];
    const float* c1w = (const float*)d_in[3];
    const float* c1b = (const float*)d_in[4];
    const float* giw = (const float*)d_in[5];
    const float* gib = (const float*)d_in[6];
    const float* c2w = (const float*)d_in[7];
    const float* c2b = (const float*)d_in[8];
    const float* liw = (const float*)d_in[9];
    const float* lib = (const float*)d_in[10];
    const float* c3w = (const float*)d_in[11];
    const float* c3b = (const float*)d_in[12];
    const float* c4w = (const float*)d_in[13];
    const float* c4b = (const float*)d_in[14];
    const float* f1w = (const float*)d_in[15];
    const float* f1b = (const float*)d_in[16];
    const float* hw  = (const float*)d_in[17];
    const float* hb  = (const float*)d_in[18];

    float* out = (float*)d_out;          // [B,1] first
    float* cs  = out + B_;               // then csamples [B,L]

    const int SMEM1 = (100 * 132 + 50 * 128) * 4;    // 78.4 KB -> 2 CTAs/SM
    const int SMEM3 = (200 * 84 + 10000) * 4;        // 107.2 KB -> 2 CTAs/SM
    cudaFuncSetAttribute(k1_conv1, cudaFuncAttributeMaxDynamicSharedMemorySize, SMEM1);
    cudaFuncSetAttribute(k3_main, cudaFuncAttributeMaxDynamicSharedMemorySize, SMEM3);

    k0_prep<<<(3 * 100 * 128 + 255) / 256, 256>>>(c1w, c2w, liw);
    k1_conv1<<<dim3(L_ / 128, B_), 256, SMEM1>>>(x, emb, c1b);
    k2_gz<<<B_, 128>>>(giw, gib, c3w, c3b);
    k3_main<<<dim3(L_ / 64, B_), 256, SMEM3>>>(c2b, lib, c3w, c4w, c4b);
    k4_init<<<(B_ * L_ + 255) / 256, 256>>>(cs);
    k4_gumbel<<<dim3(KK_, B_), 256>>>(u, cs);
    k5_final<<<B_, 128>>>(x, emb, f1w, f1b, hw, hb, cs, out);
}

// round 5
// speedup vs baseline: 3.9345x; 3.8384x over previous
#include <cuda_runtime.h>
#include <cuda_bf16.h>
#include <mma.h>
#include <math.h>
#include <stdint.h>

#define B_   512
#define L_   512
#define KK_  10

using namespace nvcuda;

// ---------------- scratch (device globals; no allocations) ----------------
__device__ uint32_t g_h1[B_ * L_ * 56];          // h1 bf16x2 [b][l][112ch]
__device__ uint32_t g_h2[B_ * L_ * 56];          // h2 bf16x2
__device__ float    g_logits[B_ * L_];
__device__ float    g_hpart[B_ * 4 * 128];       // per-chunk hmean partials
__device__ float    g_gz[B_ * 128];
__device__ __nv_bfloat16 g_Wb1[3 * 128 * 112];   // [tap][f pad128][k pad112]
__device__ __nv_bfloat16 g_Wb2[3 * 128 * 112];
__device__ __nv_bfloat16 g_WbL[3 * 128 * 112];
__device__ __nv_bfloat16 g_Wb3[128 * 112];       // conv3 loc half

// ---------------- K0: weight prep -> bf16 blobs ----------------------------
__global__ void k0_prep(const float* __restrict__ w1, const float* __restrict__ w2,
                        const float* __restrict__ wl, const float* __restrict__ w3) {
    int id = blockIdx.x * 256 + threadIdx.x;
    if (id >= 143360) return;
    if (id < 129024) {
        int conv = id / 43008, rem = id - conv * 43008;
        int t = rem / 14336, p = rem - t * 14336;
        int f = p / 112, k = p - f * 112;
        float v = 0.f;
        const float* src = (conv == 0) ? w1 : (conv == 1) ? w2 : wl;
        if (f < 100 && k < 100) v = src[f * 300 + k * 3 + t];
        __nv_bfloat16* dst = (conv == 0) ? g_Wb1 : (conv == 1) ? g_Wb2 : g_WbL;
        dst[t * 14336 + f * 112 + k] = __float2bfloat16(v);
    } else {
        int p = id - 129024;
        int f = p / 112, k = p - f * 112;
        float v = 0.f;
        if (f < 100 && k < 100) v = w3[f * 200 + 100 + k];
        g_Wb3[f * 112 + k] = __float2bfloat16(v);
    }
}

// ---------------- wmma conv GEMM core ---------------------------------------
// C[f][l] = sum_{t<NT, k<112} W[t][f][k] * sData[(l+t)][k]
// warps 2(f) x 4(l); each warp 64f x 32l. B is col_major with ldm=112:
// element (k, row) at sData[k + row*112]. Tap = row offset.
template <int NT>
__device__ __forceinline__ void conv_mma(const __nv_bfloat16* __restrict__ W,
                                         const __nv_bfloat16* sData,
                                         float* sC, int wid) {
    const int wf = wid >> 2, wl = wid & 3;
    wmma::fragment<wmma::accumulator, 16, 16, 16, float> c[4][2];
#pragma unroll
    for (int i = 0; i < 4; i++)
#pragma unroll
        for (int j = 0; j < 2; j++) wmma::fill_fragment(c[i][j], 0.f);
#pragma unroll
    for (int t = 0; t < NT; t++) {
        for (int ks = 0; ks < 7; ks++) {
            wmma::fragment<wmma::matrix_b, 16, 16, 16, __nv_bfloat16, wmma::col_major> bf[2];
#pragma unroll
            for (int j = 0; j < 2; j++)
                wmma::load_matrix_sync(bf[j], sData + ks * 16 + (wl * 32 + j * 16 + t) * 112, 112);
#pragma unroll
            for (int i = 0; i < 4; i++) {
                wmma::fragment<wmma::matrix_a, 16, 16, 16, __nv_bfloat16, wmma::row_major> af;
                wmma::load_matrix_sync(af, W + t * 14336 + (wf * 64 + i * 16) * 112 + ks * 16, 112);
#pragma unroll
                for (int j = 0; j < 2; j++) wmma::mma_sync(c[i][j], af, bf[j], c[i][j]);
            }
        }
    }
    // C col_major: addr = f + l*132  -> sC[l][f]
#pragma unroll
    for (int i = 0; i < 4; i++)
#pragma unroll
        for (int j = 0; j < 2; j++)
            wmma::store_matrix_sync(sC + (wf * 64 + i * 16) + (wl * 32 + j * 16) * 132,
                                    c[i][j], 132, wmma::mem_col_major);
}

// smem map (bytes): data [130][112]bf16 @0 (29120) | C [128l][132f]f32 @29120 (67584)
// | bias @96704 (512) | gz @97216 (512) | c4 @97728 (512)
#define SM_C     29120
#define SM_BIAS  96704
#define SM_GZ    97216
#define SM_C4    97728
#define CONV_SMEM 98304

// ---------------- KC1: emb gather + conv1 -> h1 + hmean partials -----------
__global__ __launch_bounds__(256, 2) void kC1(const int* __restrict__ x,
                                              const float* __restrict__ emb,
                                              const float* __restrict__ b1) {
    extern __shared__ char sm[];
    __nv_bfloat16* sData = (__nv_bfloat16*)sm;
    uint32_t* sD32 = (uint32_t*)sm;
    float* sC = (float*)(sm + SM_C);
    float* sBias = (float*)(sm + SM_BIAS);
    const int cx = blockIdx.x, b = blockIdx.y, tid = threadIdx.x;
    const int l0 = cx * 128;
    const int* xb = x + b * L_;

    for (int idx = tid; idx < 130 * 56; idx += 256) {
        int r = idx / 56, c = idx - r * 56;
        int l = l0 - 1 + r;
        uint32_t pk = 0;
        if ((unsigned)l < (unsigned)L_) {
            int e0 = c * 2;
            if (e0 < 100) {
                int tok = xb[l];
                float v0 = emb[tok * 100 + e0];
                float v1 = (e0 + 1 < 100) ? emb[tok * 100 + e0 + 1] : 0.f;
                __nv_bfloat162 bp = __floats2bfloat162_rn(v0, v1);
                pk = *reinterpret_cast<uint32_t*>(&bp);
            }
        }
        sD32[r * 56 + c] = pk;
    }
    if (tid < 128) sBias[tid] = (tid < 100) ? b1[tid] : 0.f;
    __syncthreads();

    conv_mma<3>(g_Wb1, sData, sC, tid >> 5);
    __syncthreads();

    if (tid < 128) {
        const float* cr = sC + tid * 132;
        uint32_t pk[56];
#pragma unroll
        for (int f = 0; f < 112; f += 2) {
            float v0 = fmaxf(cr[f] + sBias[f], 0.f);
            float v1 = fmaxf(cr[f + 1] + sBias[f + 1], 0.f);
            __nv_bfloat162 bp = __floats2bfloat162_rn(v0, v1);
            pk[f >> 1] = *reinterpret_cast<uint32_t*>(&bp);
        }
        uint4* d4 = (uint4*)(g_h1 + ((size_t)b * L_ + l0 + tid) * 56);
#pragma unroll
        for (int q = 0; q < 14; q++)
            d4[q] = make_uint4(pk[4 * q], pk[4 * q + 1], pk[4 * q + 2], pk[4 * q + 3]);
        // hmean partial for f = tid over this chunk's 128 positions
        float bb = sBias[tid];
        float s = 0.f;
        for (int l = 0; l < 128; l++) s += fmaxf(sC[tid + l * 132] + bb, 0.f);
        g_hpart[(b * 4 + cx) * 128 + tid] = s;
    }
}

// ---------------- KG: hmean -> g -> gz -------------------------------------
__global__ __launch_bounds__(128) void kG(const float* __restrict__ giw,
                                          const float* __restrict__ gib,
                                          const float* __restrict__ c3w,
                                          const float* __restrict__ c3b) {
    const int b = blockIdx.x, tid = threadIdx.x;
    __shared__ float shm[100], sg[100];
    if (tid < 100) {
        const float* p = g_hpart + b * 4 * 128 + tid;
        shm[tid] = (p[0] + p[128] + p[256] + p[384]) * (1.f / (float)L_);
    }
    __syncthreads();
    if (tid < 100) {
        float a = gib[tid];
        const float* wr = &giw[tid * 100];
        for (int f = 0; f < 100; f++) a = fmaf(wr[f], shm[f], a);
        sg[tid] = fmaxf(a, 0.f);
    }
    __syncthreads();
    if (tid < 100) {
        float a = c3b[tid];
        const float* wr = &c3w[tid * 200];
        for (int h = 0; h < 100; h++) a = fmaf(wr[h], sg[h], a);
        g_gz[b * 128 + tid] = a;
    }
}

// ---------------- KC2: conv2 (h1 -> h2) ------------------------------------
__global__ __launch_bounds__(256, 2) void kC2(const float* __restrict__ b2) {
    extern __shared__ char sm[];
    __nv_bfloat16* sData = (__nv_bfloat16*)sm;
    float* sC = (float*)(sm + SM_C);
    float* sBias = (float*)(sm + SM_BIAS);
    const int cx = blockIdx.x, b = blockIdx.y, tid = threadIdx.x;
    const int l0 = cx * 128;
    const uint4* src = (const uint4*)(g_h1 + (size_t)b * L_ * 56);

    for (int idx = tid; idx < 130 * 14; idx += 256) {
        int r = idx / 14, q = idx - r * 14;
        int l = l0 - 1 + r;
        uint4 v = make_uint4(0, 0, 0, 0);
        if ((unsigned)l < (unsigned)L_) v = src[l * 14 + q];
        ((uint4*)sm)[r * 14 + q] = v;
    }
    if (tid < 128) sBias[tid] = (tid < 100) ? b2[tid] : 0.f;
    __syncthreads();

    conv_mma<3>(g_Wb2, sData, sC, tid >> 5);
    __syncthreads();

    if (tid < 128) {
        const float* cr = sC + tid * 132;
        uint32_t pk[56];
#pragma unroll
        for (int f = 0; f < 112; f += 2) {
            float v0 = fmaxf(cr[f] + sBias[f], 0.f);
            float v1 = fmaxf(cr[f + 1] + sBias[f + 1], 0.f);
            __nv_bfloat162 bp = __floats2bfloat162_rn(v0, v1);
            pk[f >> 1] = *reinterpret_cast<uint32_t*>(&bp);
        }
        uint4* d4 = (uint4*)(g_h2 + ((size_t)b * L_ + l0 + tid) * 56);
#pragma unroll
        for (int q = 0; q < 14; q++)
            d4[q] = make_uint4(pk[4 * q], pk[4 * q + 1], pk[4 * q + 2], pk[4 * q + 3]);
    }
}

// ---------------- KC3: li conv -> conv3(loc)+gz -> conv4 -> logits ---------
__global__ __launch_bounds__(256, 2) void kC3(const float* __restrict__ lb,
                                              const float* __restrict__ c4w,
                                              const float* __restrict__ c4b) {
    extern __shared__ char sm[];
    __nv_bfloat16* sData = (__nv_bfloat16*)sm;
    uint32_t* sD32 = (uint32_t*)sm;
    float* sC = (float*)(sm + SM_C);
    float* sBias = (float*)(sm + SM_BIAS);
    float* sGz = (float*)(sm + SM_GZ);
    float* sC4 = (float*)(sm + SM_C4);
    const int cx = blockIdx.x, b = blockIdx.y, tid = threadIdx.x;
    const int l0 = cx * 128;
    const uint4* src = (const uint4*)(g_h2 + (size_t)b * L_ * 56);

    for (int idx = tid; idx < 130 * 14; idx += 256) {
        int r = idx / 14, q = idx - r * 14;
        int l = l0 - 1 + r;
        uint4 v = make_uint4(0, 0, 0, 0);
        if ((unsigned)l < (unsigned)L_) v = src[l * 14 + q];
        ((uint4*)sm)[r * 14 + q] = v;
    }
    if (tid < 128) {
        sBias[tid] = (tid < 100) ? lb[tid] : 0.f;
        sGz[tid] = (tid < 100) ? g_gz[b * 128 + tid] : 0.f;
        sC4[tid] = (tid < 100) ? c4w[tid] : 0.f;
    }
    __syncthreads();

    conv_mma<3>(g_WbL, sData, sC, tid >> 5);       // li conv
    __syncthreads();

    // Loc = relu(C + lb) packed bf16 -> sData [128 l][112]
    if (tid < 128) {
        const float* cr = sC + tid * 132;
        uint32_t pk[56];
#pragma unroll
        for (int f = 0; f < 112; f += 2) {
            float v0 = fmaxf(cr[f] + sBias[f], 0.f);
            float v1 = fmaxf(cr[f + 1] + sBias[f + 1], 0.f);
            __nv_bfloat162 bp = __floats2bfloat162_rn(v0, v1);
            pk[f >> 1] = *reinterpret_cast<uint32_t*>(&bp);
        }
#pragma unroll
        for (int c = 0; c < 56; c++) sD32[tid * 56 + c] = pk[c];
    }
    __syncthreads();

    conv_mma<1>(g_Wb3, sData, sC, tid >> 5);       // conv3 loc half
    __syncthreads();

    if (tid < 128) {
        const float* cr = sC + tid * 132;
        float logit = 0.f;
#pragma unroll 4
        for (int f = 0; f < 128; f++)
            logit += sC4[f] * fmaxf(cr[f] + sGz[f], 0.f);
        g_logits[b * L_ + l0 + tid] = logit + c4b[0];
    }
}

// ---------------- reductions -----------------------------------------------
__device__ __forceinline__ float bmax256(float v, float* sred) {
#pragma unroll
    for (int o = 16; o > 0; o >>= 1) v = fmaxf(v, __shfl_xor_sync(0xffffffffu, v, o));
    int w = threadIdx.x >> 5;
    if ((threadIdx.x & 31) == 0) sred[w] = v;
    __syncthreads();
    if (threadIdx.x == 0) {
        float t = sred[0];
#pragma unroll
        for (int i = 1; i < 8; i++) t = fmaxf(t, sred[i]);
        sred[0] = t;
    }
    __syncthreads();
    float r = sred[0];
    __syncthreads();
    return r;
}
__device__ __forceinline__ float bsum256(float v, float* sred) {
#pragma unroll
    for (int o = 16; o > 0; o >>= 1) v += __shfl_xor_sync(0xffffffffu, v, o);
    int w = threadIdx.x >> 5;
    if ((threadIdx.x & 31) == 0) sred[w] = v;
    __syncthreads();
    if (threadIdx.x == 0) {
        float t = sred[0];
#pragma unroll
        for (int i = 1; i < 8; i++) t += sred[i];
        sred[0] = t;
    }
    __syncthreads();
    float r = sred[0];
    __syncthreads();
    return r;
}

// ---------------- K4: gumbel softmax over L, max over K --------------------
__global__ __launch_bounds__(256) void k4_init(float* __restrict__ cs) {
    int i = blockIdx.x * 256 + threadIdx.x;
    if (i < B_ * L_) cs[i] = 0.f;
}
__global__ __launch_bounds__(256) void k4_gumbel(const float* __restrict__ u,
                                                 float* __restrict__ cs_out) {
    const int k = blockIdx.x, b = blockIdx.y, tid = threadIdx.x;
    __shared__ float sred[8];
    const float EPS = 1.1920929e-07f;
    const float invT = 1.0f / 0.3f;
    const float* lg = g_logits + b * L_;
    const float* ub = u + (b * KK_ + k) * L_;
    float u0 = ub[tid], u1 = ub[tid + 256];
    u0 = fminf(fmaxf(u0, EPS), 1.0f - EPS);
    u1 = fminf(fmaxf(u1, EPS), 1.0f - EPS);
    float nv0 = (-logf(-logf(u0)) + lg[tid]) * invT;
    float nv1 = (-logf(-logf(u1)) + lg[tid + 256]) * invT;
    float m = bmax256(fmaxf(nv0, nv1), sred);
    float e0 = expf(nv0 - m), e1 = expf(nv1 - m);
    float s = bsum256(e0 + e1, sred);
    float rs = 1.f / s;
    atomicMax((int*)&cs_out[b * L_ + tid], __float_as_int(e0 * rs));
    atomicMax((int*)&cs_out[b * L_ + tid + 256], __float_as_int(e1 * rs));
}

// ---------------- K5: weighted pooling + MLP + sigmoid ---------------------
__global__ __launch_bounds__(128) void k5_final(const int* __restrict__ x,
                                                const float* __restrict__ emb,
                                                const float* __restrict__ f1w,
                                                const float* __restrict__ f1b,
                                                const float* __restrict__ hw,
                                                const float* __restrict__ hb,
                                                const float* __restrict__ cs,
                                                float* __restrict__ out) {
    const int b = blockIdx.x, tid = threadIdx.x;
    __shared__ float scs[L_];
    __shared__ int sx[L_];
    __shared__ float spool[100];
    __shared__ float sh[100];
    __shared__ float sred[4];
    for (int l = tid; l < L_; l += 128) {
        scs[l] = cs[b * L_ + l];
        sx[l] = x[b * L_ + l];
    }
    __syncthreads();
    if (tid < 100) {
        float acc = 0.f;
        for (int l = 0; l < L_; l += 8) {
            float p[8];
#pragma unroll
            for (int q = 0; q < 8; q++) p[q] = emb[sx[l + q] * 100 + tid];
#pragma unroll
            for (int q = 0; q < 8; q++) acc = fmaf(scs[l + q], p[q], acc);
        }
        spool[tid] = acc * (1.f / (float)L_);
    }
    __syncthreads();
    if (tid < 100) {
        float a = f1b[tid];
        const float* wr = &f1w[tid * 100];
        for (int e = 0; e < 100; e++) a = fmaf(wr[e], spool[e], a);
        sh[tid] = fmaxf(a, 0.f);
    }
    __syncthreads();
    float hv = (tid < 100) ? hw[tid] * sh[tid] : 0.f;
#pragma unroll
    for (int o = 16; o > 0; o >>= 1) hv += __shfl_xor_sync(0xffffffffu, hv, o);
    if ((tid & 31) == 0) sred[tid >> 5] = hv;
    __syncthreads();
    if (tid == 0) {
        float t = sred[0] + sred[1] + sred[2] + sred[3] + hb[0];
        out[b] = 1.f / (1.f + expf(-t));
    }
}

// ---------------- launch ----------------------------------------------------
extern "C" void kernel_launch(void* const* d_in, const int* in_sizes, int n_in,
                              void* d_out, int out_size) {
    const int*   x   = (const int*)  d_in[0];
    const float* u   = (const float*)d_in[1];
    const float* emb = (const float*)d_in[2];
    const float* c1w = (const float*)d_in[3];
    const float* c1b = (const float*)d_in[4];
    const float* giw = (const float*)d_in[5];
    const float* gib = (const float*)d_in[6];
    const float* c2w = (const float*)d_in[7];
    const float* c2b = (const float*)d_in[8];
    const float* liw = (const float*)d_in[9];
    const float* lib = (const float*)d_in[10];
    const float* c3w = (const float*)d_in[11];
    const float* c3b = (const float*)d_in[12];
    const float* c4w = (const float*)d_in[13];
    const float* c4b = (const float*)d_in[14];
    const float* f1w = (const float*)d_in[15];
    const float* f1b = (const float*)d_in[16];
    const float* hw  = (const float*)d_in[17];
    const float* hb  = (const float*)d_in[18];

    float* out = (float*)d_out;          // [B,1] first
    float* cs  = out + B_;               // then csamples [B,L]

    cudaFuncSetAttribute(kC1, cudaFuncAttributeMaxDynamicSharedMemorySize, CONV_SMEM);
    cudaFuncSetAttribute(kC2, cudaFuncAttributeMaxDynamicSharedMemorySize, CONV_SMEM);
    cudaFuncSetAttribute(kC3, cudaFuncAttributeMaxDynamicSharedMemorySize, CONV_SMEM);

    k0_prep<<<(143360 + 255) / 256, 256>>>(c1w, c2w, liw, c3w);
    kC1<<<dim3(4, B_), 256, CONV_SMEM>>>(x, emb, c1b);
    kG<<<B_, 128>>>(giw, gib, c3w, c3b);
    kC2<<<dim3(4, B_), 256, CONV_SMEM>>>(c2b);
    kC3<<<dim3(4, B_), 256, CONV_SMEM>>>(lib, c4w, c4b);
    k4_init<<<(B_ * L_ + 255) / 256, 256>>>(cs);
    k4_gumbel<<<dim3(KK_, B_), 256>>>(u, cs);
    k5_final<<<B_, 128>>>(x, emb, f1w, f1b, hw, hb, cs, out);
}

// round 6
// speedup vs baseline: 4.4512x; 1.1313x over previous
#include <cuda_runtime.h>
#include <cuda_bf16.h>
#include <mma.h>
#include <math.h>
#include <stdint.h>

#define B_   512
#define L_   512
#define KK_  10

using namespace nvcuda;

// ---------------- scratch (device globals; no allocations) ----------------
__device__ uint32_t g_h1[B_ * L_ * 56];          // h1 bf16x2 [b][l][112ch]
__device__ uint32_t g_h2[B_ * L_ * 56];
__device__ float    g_logits[B_ * L_];
__device__ float    g_hpart[B_ * 4 * 128];
__device__ float    g_gz[B_ * 128];
__device__ __nv_bfloat16 g_Wb1[3 * 128 * 120];   // [tap][f pad128][k pad120]
__device__ __nv_bfloat16 g_Wb2[3 * 128 * 120];
__device__ __nv_bfloat16 g_WbL[3 * 128 * 120];
__device__ __nv_bfloat16 g_Wb3[128 * 120];       // conv3 loc half

// ---------------- K0: weight prep -> padded bf16 blobs ---------------------
__global__ void k0_prep(const float* __restrict__ w1, const float* __restrict__ w2,
                        const float* __restrict__ wl, const float* __restrict__ w3) {
    int id = blockIdx.x * 256 + threadIdx.x;
    if (id >= 153600) return;
    if (id < 138240) {
        int conv = id / 46080, rem = id - conv * 46080;
        int t = rem / 15360, p = rem - t * 15360;
        int f = p / 120, k = p - f * 120;
        float v = 0.f;
        const float* src = (conv == 0) ? w1 : (conv == 1) ? w2 : wl;
        if (f < 100 && k < 100) v = src[f * 300 + k * 3 + t];
        __nv_bfloat16* dst = (conv == 0) ? g_Wb1 : (conv == 1) ? g_Wb2 : g_WbL;
        dst[t * 15360 + f * 120 + k] = __float2bfloat16(v);
    } else {
        int p = id - 138240;
        int f = p / 120, k = p - f * 120;
        float v = 0.f;
        if (f < 100 && k < 100) v = w3[f * 200 + 100 + k];
        g_Wb3[f * 120 + k] = __float2bfloat16(v);
    }
}

// ---------------- smem map (bytes) -----------------------------------------
// data [130][120]bf16 @0 (31200) | wtap [128][120]bf16 @31200 (30720)
// | C [64l][132f]f32 @61920 (33792) | bias @95712 | gz @96224 | c4 @96736
#define SM_W     31200
#define SM_C2    61920
#define SM_BIAS  95712
#define SM_GZ    96224
#define SM_C4    96736
#define CONV_SMEM 97248

// ---------------- wmma conv GEMM core --------------------------------------
// C[f][l] = sum_{t<NT,k<112} W[t][f][k] * sData[(l+t)][k]
// Weights staged per-tap into sW (smem). warps 2(f) x 4(l), warp = 64f x 32l.
// A row-major ldm=120 from sW; B col_major ldm=120 from sData. Both LDSM
// conflict-free (240B row stride -> distinct banks mod 128B).
template <int NT>
__device__ __forceinline__ void conv_mma(
    const __nv_bfloat16* __restrict__ Wg, const __nv_bfloat16* sData,
    __nv_bfloat16* sW,
    wmma::fragment<wmma::accumulator, 16, 16, 16, float> (&c)[4][2], int tid) {
    const int wid = tid >> 5, wf = wid >> 2, wl = wid & 3;
#pragma unroll
    for (int i = 0; i < 4; i++)
#pragma unroll
        for (int j = 0; j < 2; j++) wmma::fill_fragment(c[i][j], 0.f);
#pragma unroll
    for (int t = 0; t < NT; t++) {
        __syncthreads();                       // sW free / sData ready
        for (int idx = tid; idx < 1920; idx += 256)
            ((uint4*)sW)[idx] = ((const uint4*)(Wg + t * 15360))[idx];
        __syncthreads();
#pragma unroll
        for (int ks = 0; ks < 7; ks++) {
            wmma::fragment<wmma::matrix_b, 16, 16, 16, __nv_bfloat16, wmma::col_major> bf[2];
#pragma unroll
            for (int j = 0; j < 2; j++)
                wmma::load_matrix_sync(bf[j], sData + ks * 16 + (wl * 32 + j * 16 + t) * 120, 120);
#pragma unroll
            for (int i = 0; i < 4; i++) {
                wmma::fragment<wmma::matrix_a, 16, 16, 16, __nv_bfloat16, wmma::row_major> af;
                wmma::load_matrix_sync(af, sW + (wf * 64 + i * 16) * 120 + ks * 16, 120);
#pragma unroll
                for (int j = 0; j < 2; j++) wmma::mma_sync(c[i][j], af, bf[j], c[i][j]);
            }
        }
    }
}

// ---------------- KC1: emb gather + conv1 -> h1 + hmean partials -----------
__global__ __launch_bounds__(256, 2) void kC1(const int* __restrict__ x,
                                              const float* __restrict__ emb,
                                              const float* __restrict__ b1) {
    extern __shared__ char sm[];
    __nv_bfloat16* sData = (__nv_bfloat16*)sm;
    uint32_t* sD32 = (uint32_t*)sm;
    __nv_bfloat16* sW = (__nv_bfloat16*)(sm + SM_W);
    float* sC2 = (float*)(sm + SM_C2);
    float* sBias = (float*)(sm + SM_BIAS);
    const int cx = blockIdx.x, b = blockIdx.y, tid = threadIdx.x;
    const int l0 = cx * 128;
    const int* xb = x + b * L_;

    for (int idx = tid; idx < 130 * 60; idx += 256) {
        int r = idx / 60, cpr = idx - r * 60;
        int l = l0 - 1 + r;
        uint32_t pk = 0;
        if ((unsigned)l < (unsigned)L_ && cpr < 50) {
            int tok = xb[l];
            float v0 = emb[tok * 100 + 2 * cpr];
            float v1 = emb[tok * 100 + 2 * cpr + 1];
            __nv_bfloat162 bp = __floats2bfloat162_rn(v0, v1);
            pk = *reinterpret_cast<uint32_t*>(&bp);
        }
        sD32[r * 60 + cpr] = pk;
    }
    if (tid < 128) sBias[tid] = (tid < 100) ? b1[tid] : 0.f;

    wmma::fragment<wmma::accumulator, 16, 16, 16, float> c[4][2];
    conv_mma<3>(g_Wb1, sData, sW, c, tid);

    const int wid = tid >> 5, wf = wid >> 2, wl = wid & 3;
    float msum = 0.f;
#pragma unroll
    for (int p = 0; p < 2; p++) {
        if ((wl >> 1) == p) {
#pragma unroll
            for (int i = 0; i < 4; i++)
#pragma unroll
                for (int j = 0; j < 2; j++)
                    wmma::store_matrix_sync(sC2 + (wf * 64 + i * 16) + ((wl & 1) * 32 + j * 16) * 132,
                                            c[i][j], 132, wmma::mem_col_major);
        }
        __syncthreads();
        if (tid < 128) {
            int lr = tid >> 1, half = tid & 1;
            const float* cr = sC2 + lr * 132 + half * 56;
            const float* bb = sBias + half * 56;
            uint32_t pk[28];
#pragma unroll
            for (int q = 0; q < 28; q++) {
                float v0 = fmaxf(cr[2 * q] + bb[2 * q], 0.f);
                float v1 = fmaxf(cr[2 * q + 1] + bb[2 * q + 1], 0.f);
                __nv_bfloat162 bp = __floats2bfloat162_rn(v0, v1);
                pk[q] = *reinterpret_cast<uint32_t*>(&bp);
            }
            uint4* d4 = (uint4*)(g_h1 + ((size_t)b * L_ + l0 + p * 64 + lr) * 56 + half * 28);
#pragma unroll
            for (int q = 0; q < 7; q++)
                d4[q] = make_uint4(pk[4 * q], pk[4 * q + 1], pk[4 * q + 2], pk[4 * q + 3]);
            // hmean partial over these 64 rows for f = tid
            float bf_ = sBias[tid], s = 0.f;
            for (int l = 0; l < 64; l++) s += fmaxf(sC2[tid + l * 132] + bf_, 0.f);
            msum += s;
        }
        __syncthreads();
    }
    if (tid < 128) g_hpart[(b * 4 + cx) * 128 + tid] = msum;
}

// ---------------- KG: hmean -> g -> gz -------------------------------------
__global__ __launch_bounds__(128) void kG(const float* __restrict__ giw,
                                          const float* __restrict__ gib,
                                          const float* __restrict__ c3w,
                                          const float* __restrict__ c3b) {
    const int b = blockIdx.x, tid = threadIdx.x;
    __shared__ float shm[100], sg[100];
    if (tid < 100) {
        const float* p = g_hpart + b * 4 * 128 + tid;
        shm[tid] = (p[0] + p[128] + p[256] + p[384]) * (1.f / (float)L_);
    }
    __syncthreads();
    if (tid < 100) {
        float a = gib[tid];
        const float* wr = &giw[tid * 100];
        for (int f = 0; f < 100; f++) a = fmaf(wr[f], shm[f], a);
        sg[tid] = fmaxf(a, 0.f);
    }
    __syncthreads();
    if (tid < 100) {
        float a = c3b[tid];
        const float* wr = &c3w[tid * 200];
        for (int h = 0; h < 100; h++) a = fmaf(wr[h], sg[h], a);
        g_gz[b * 128 + tid] = a;
    }
}

// ---------------- KC2: conv2 (h1 -> h2) ------------------------------------
__global__ __launch_bounds__(256, 2) void kC2(const float* __restrict__ b2) {
    extern __shared__ char sm[];
    __nv_bfloat16* sData = (__nv_bfloat16*)sm;
    __nv_bfloat16* sW = (__nv_bfloat16*)(sm + SM_W);
    float* sC2 = (float*)(sm + SM_C2);
    float* sBias = (float*)(sm + SM_BIAS);
    const int cx = blockIdx.x, b = blockIdx.y, tid = threadIdx.x;
    const int l0 = cx * 128;
    const uint4* src = (const uint4*)(g_h1 + (size_t)b * L_ * 56);

    for (int idx = tid; idx < 130 * 15; idx += 256) {
        int r = idx / 15, q = idx - r * 15;
        int l = l0 - 1 + r;
        uint4 v = make_uint4(0, 0, 0, 0);
        if (q < 14 && (unsigned)l < (unsigned)L_) v = src[l * 14 + q];
        ((uint4*)sm)[r * 15 + q] = v;
    }
    if (tid < 128) sBias[tid] = (tid < 100) ? b2[tid] : 0.f;

    wmma::fragment<wmma::accumulator, 16, 16, 16, float> c[4][2];
    conv_mma<3>(g_Wb2, sData, sW, c, tid);

    const int wid = tid >> 5, wf = wid >> 2, wl = wid & 3;
#pragma unroll
    for (int p = 0; p < 2; p++) {
        if ((wl >> 1) == p) {
#pragma unroll
            for (int i = 0; i < 4; i++)
#pragma unroll
                for (int j = 0; j < 2; j++)
                    wmma::store_matrix_sync(sC2 + (wf * 64 + i * 16) + ((wl & 1) * 32 + j * 16) * 132,
                                            c[i][j], 132, wmma::mem_col_major);
        }
        __syncthreads();
        if (tid < 128) {
            int lr = tid >> 1, half = tid & 1;
            const float* cr = sC2 + lr * 132 + half * 56;
            const float* bb = sBias + half * 56;
            uint32_t pk[28];
#pragma unroll
            for (int q = 0; q < 28; q++) {
                float v0 = fmaxf(cr[2 * q] + bb[2 * q], 0.f);
                float v1 = fmaxf(cr[2 * q + 1] + bb[2 * q + 1], 0.f);
                __nv_bfloat162 bp = __floats2bfloat162_rn(v0, v1);
                pk[q] = *reinterpret_cast<uint32_t*>(&bp);
            }
            uint4* d4 = (uint4*)(g_h2 + ((size_t)b * L_ + l0 + p * 64 + lr) * 56 + half * 28);
#pragma unroll
            for (int q = 0; q < 7; q++)
                d4[q] = make_uint4(pk[4 * q], pk[4 * q + 1], pk[4 * q + 2], pk[4 * q + 3]);
        }
        __syncthreads();
    }
}

// ---------------- KC3: li conv -> conv3(loc)+gz -> conv4 -> logits ---------
__global__ __launch_bounds__(256, 2) void kC3(const float* __restrict__ lb,
                                              const float* __restrict__ c4w,
                                              const float* __restrict__ c4b) {
    extern __shared__ char sm[];
    __nv_bfloat16* sData = (__nv_bfloat16*)sm;
    uint32_t* sD32 = (uint32_t*)sm;
    __nv_bfloat16* sW = (__nv_bfloat16*)(sm + SM_W);
    float* sC2 = (float*)(sm + SM_C2);
    float* sBias = (float*)(sm + SM_BIAS);
    float* sGz = (float*)(sm + SM_GZ);
    float* sC4 = (float*)(sm + SM_C4);
    const int cx = blockIdx.x, b = blockIdx.y, tid = threadIdx.x;
    const int l0 = cx * 128;
    const uint4* src = (const uint4*)(g_h2 + (size_t)b * L_ * 56);

    for (int idx = tid; idx < 130 * 15; idx += 256) {
        int r = idx / 15, q = idx - r * 15;
        int l = l0 - 1 + r;
        uint4 v = make_uint4(0, 0, 0, 0);
        if (q < 14 && (unsigned)l < (unsigned)L_) v = src[l * 14 + q];
        ((uint4*)sm)[r * 15 + q] = v;
    }
    if (tid < 128) {
        sBias[tid] = (tid < 100) ? lb[tid] : 0.f;
        sGz[tid] = (tid < 100) ? g_gz[b * 128 + tid] : 0.f;
        sC4[tid] = (tid < 100) ? c4w[tid] : 0.f;
    }

    wmma::fragment<wmma::accumulator, 16, 16, 16, float> c[4][2];
    conv_mma<3>(g_WbL, sData, sW, c, tid);

    const int wid = tid >> 5, wf = wid >> 2, wl = wid & 3;
    // Loc = relu(C + lb) -> bf16 pairs back into sData rows 0..127
#pragma unroll
    for (int p = 0; p < 2; p++) {
        if ((wl >> 1) == p) {
#pragma unroll
            for (int i = 0; i < 4; i++)
#pragma unroll
                for (int j = 0; j < 2; j++)
                    wmma::store_matrix_sync(sC2 + (wf * 64 + i * 16) + ((wl & 1) * 32 + j * 16) * 132,
                                            c[i][j], 132, wmma::mem_col_major);
        }
        __syncthreads();
        if (tid < 128) {
            int lr = tid >> 1, half = tid & 1;
            const float* cr = sC2 + lr * 132 + half * 56;
            const float* bb = sBias + half * 56;
            uint32_t pk[28];
#pragma unroll
            for (int q = 0; q < 28; q++) {
                float v0 = fmaxf(cr[2 * q] + bb[2 * q], 0.f);
                float v1 = fmaxf(cr[2 * q + 1] + bb[2 * q + 1], 0.f);
                __nv_bfloat162 bp = __floats2bfloat162_rn(v0, v1);
                pk[q] = *reinterpret_cast<uint32_t*>(&bp);
            }
            uint4* d4 = (uint4*)(sD32 + (size_t)(p * 64 + lr) * 60 + half * 28);
#pragma unroll
            for (int q = 0; q < 7; q++)
                d4[q] = make_uint4(pk[4 * q], pk[4 * q + 1], pk[4 * q + 2], pk[4 * q + 3]);
        }
        __syncthreads();
    }
    // zero pad channels 112..119 for rows 0..127
    for (int idx = tid; idx < 128 * 4; idx += 256) {
        int r = idx >> 2;
        sD32[r * 60 + 56 + (idx & 3)] = 0;
    }

    conv_mma<1>(g_Wb3, sData, sW, c, tid);   // conv3 loc half (1x1)

    const float c4bias = c4b[0];
#pragma unroll
    for (int p = 0; p < 2; p++) {
        if ((wl >> 1) == p) {
#pragma unroll
            for (int i = 0; i < 4; i++)
#pragma unroll
                for (int j = 0; j < 2; j++)
                    wmma::store_matrix_sync(sC2 + (wf * 64 + i * 16) + ((wl & 1) * 32 + j * 16) * 132,
                                            c[i][j], 132, wmma::mem_col_major);
        }
        __syncthreads();
        if (tid < 128) {
            int lr = tid >> 1, half = tid & 1;
            const float* cr = sC2 + lr * 132 + half * 64;
            const float* gz = sGz + half * 64;
            const float* c4 = sC4 + half * 64;
            float part = 0.f;
#pragma unroll 8
            for (int f = 0; f < 64; f++)
                part += c4[f] * fmaxf(cr[f] + gz[f], 0.f);
            part += __shfl_xor_sync(0xffffffffu, part, 1);
            if (half == 0) g_logits[b * L_ + l0 + p * 64 + lr] = part + c4bias;
        }
        __syncthreads();
    }
}

// ---------------- reductions -----------------------------------------------
__device__ __forceinline__ float bmax256(float v, float* sred) {
#pragma unroll
    for (int o = 16; o > 0; o >>= 1) v = fmaxf(v, __shfl_xor_sync(0xffffffffu, v, o));
    int w = threadIdx.x >> 5;
    if ((threadIdx.x & 31) == 0) sred[w] = v;
    __syncthreads();
    if (threadIdx.x == 0) {
        float t = sred[0];
#pragma unroll
        for (int i = 1; i < 8; i++) t = fmaxf(t, sred[i]);
        sred[0] = t;
    }
    __syncthreads();
    float r = sred[0];
    __syncthreads();
    return r;
}
__device__ __forceinline__ float bsum256(float v, float* sred) {
#pragma unroll
    for (int o = 16; o > 0; o >>= 1) v += __shfl_xor_sync(0xffffffffu, v, o);
    int w = threadIdx.x >> 5;
    if ((threadIdx.x & 31) == 0) sred[w] = v;
    __syncthreads();
    if (threadIdx.x == 0) {
        float t = sred[0];
#pragma unroll
        for (int i = 1; i < 8; i++) t += sred[i];
        sred[0] = t;
    }
    __syncthreads();
    float r = sred[0];
    __syncthreads();
    return r;
}

// ---------------- K4: gumbel softmax over L, max over K --------------------
__global__ __launch_bounds__(256) void k4_init(float* __restrict__ cs) {
    int i = blockIdx.x * 256 + threadIdx.x;
    if (i < B_ * L_) cs[i] = 0.f;
}
__global__ __launch_bounds__(256) void k4_gumbel(const float* __restrict__ u,
                                                 float* __restrict__ cs_out) {
    const int k = blockIdx.x, b = blockIdx.y, tid = threadIdx.x;
    __shared__ float sred[8];
    const float EPS = 1.1920929e-07f;
    const float invT = 1.0f / 0.3f;
    const float* lg = g_logits + b * L_;
    const float* ub = u + (b * KK_ + k) * L_;
    float u0 = ub[tid], u1 = ub[tid + 256];
    u0 = fminf(fmaxf(u0, EPS), 1.0f - EPS);
    u1 = fminf(fmaxf(u1, EPS), 1.0f - EPS);
    float nv0 = (-logf(-logf(u0)) + lg[tid]) * invT;
    float nv1 = (-logf(-logf(u1)) + lg[tid + 256]) * invT;
    float m = bmax256(fmaxf(nv0, nv1), sred);
    float e0 = expf(nv0 - m), e1 = expf(nv1 - m);
    float s = bsum256(e0 + e1, sred);
    float rs = 1.f / s;
    atomicMax((int*)&cs_out[b * L_ + tid], __float_as_int(e0 * rs));
    atomicMax((int*)&cs_out[b * L_ + tid + 256], __float_as_int(e1 * rs));
}

// ---------------- K5: weighted pooling + MLP + sigmoid ---------------------
__global__ __launch_bounds__(128) void k5_final(const int* __restrict__ x,
                                                const float* __restrict__ emb,
                                                const float* __restrict__ f1w,
                                                const float* __restrict__ f1b,
                                                const float* __restrict__ hw,
                                                const float* __restrict__ hb,
                                                const float* __restrict__ cs,
                                                float* __restrict__ out) {
    const int b = blockIdx.x, tid = threadIdx.x;
    __shared__ float scs[L_];
    __shared__ int sx[L_];
    __shared__ float spool[100];
    __shared__ float sh[100];
    __shared__ float sred[4];
    for (int l = tid; l < L_; l += 128) {
        scs[l] = cs[b * L_ + l];
        sx[l] = x[b * L_ + l];
    }
    __syncthreads();
    if (tid < 100) {
        float acc = 0.f;
        for (int l = 0; l < L_; l += 8) {
            float p[8];
#pragma unroll
            for (int q = 0; q < 8; q++) p[q] = emb[sx[l + q] * 100 + tid];
#pragma unroll
            for (int q = 0; q < 8; q++) acc = fmaf(scs[l + q], p[q], acc);
        }
        spool[tid] = acc * (1.f / (float)L_);
    }
    __syncthreads();
    if (tid < 100) {
        float a = f1b[tid];
        const float* wr = &f1w[tid * 100];
        for (int e = 0; e < 100; e++) a = fmaf(wr[e], spool[e], a);
        sh[tid] = fmaxf(a, 0.f);
    }
    __syncthreads();
    float hv = (tid < 100) ? hw[tid] * sh[tid] : 0.f;
#pragma unroll
    for (int o = 16; o > 0; o >>= 1) hv += __shfl_xor_sync(0xffffffffu, hv, o);
    if ((tid & 31) == 0) sred[tid >> 5] = hv;
    __syncthreads();
    if (tid == 0) {
        float t = sred[0] + sred[1] + sred[2] + sred[3] + hb[0];
        out[b] = 1.f / (1.f + expf(-t));
    }
}

// ---------------- launch ----------------------------------------------------
extern "C" void kernel_launch(void* const* d_in, const int* in_sizes, int n_in,
                              void* d_out, int out_size) {
    const int*   x   = (const int*)  d_in[0];
    const float* u   = (const float*)d_in[1];
    const float* emb = (const float*)d_in[2];
    const float* c1w = (const float*)d_in[3];
    const float* c1b = (const float*)d_in[4];
    const float* giw = (const float*)d_in[5];
    const float* gib = (const float*)d_in[6];
    const float* c2w = (const float*)d_in[7];
    const float* c2b = (const float*)d_in[8];
    const float* liw = (const float*)d_in[9];
    const float* lib = (const float*)d_in[10];
    const float* c3w = (const float*)d_in[11];
    const float* c3b = (const float*)d_in[12];
    const float* c4w = (const float*)d_in[13];
    const float* c4b = (const float*)d_in[14];
    const float* f1w = (const float*)d_in[15];
    const float* f1b = (const float*)d_in[16];
    const float* hw  = (const float*)d_in[17];
    const float* hb  = (const float*)d_in[18];

    float* out = (float*)d_out;          // [B,1] first
    float* cs  = out + B_;               // then csamples [B,L]

    cudaFuncSetAttribute(kC1, cudaFuncAttributeMaxDynamicSharedMemorySize, CONV_SMEM);
    cudaFuncSetAttribute(kC2, cudaFuncAttributeMaxDynamicSharedMemorySize, CONV_SMEM);
    cudaFuncSetAttribute(kC3, cudaFuncAttributeMaxDynamicSharedMemorySize, CONV_SMEM);

    k0_prep<<<600, 256>>>(c1w, c2w, liw, c3w);
    kC1<<<dim3(4, B_), 256, CONV_SMEM>>>(x, emb, c1b);
    kG<<<B_, 128>>>(giw, gib, c3w, c3b);
    kC2<<<dim3(4, B_), 256, CONV_SMEM>>>(c2b);
    kC3<<<dim3(4, B_), 256, CONV_SMEM>>>(lib, c4w, c4b);
    k4_init<<<(B_ * L_ + 255) / 256, 256>>>(cs);
    k4_gumbel<<<dim3(KK_, B_), 256>>>(u, cs);
    k5_final<<<B_, 128>>>(x, emb, f1w, f1b, hw, hb, cs, out);
}